// round 5
// baseline (speedup 1.0000x reference)
#include <cuda_runtime.h>

// Problem shape (fixed by the reference's setup_inputs):
//   data: (B=8, T=500, C=306) f32      locs: (B=8, C=306, 2) f32
//   out:  (B, T, 100, 100) f32 = gather of nearest channel per grid bin.
#define NB   8
#define NT   500
#define NC   306
#define NG   100
#define NG2  10000       // NG*NG
#define TCHUNK 20        // t rows per gather block (NT / gridDim.y)

// Scratch: nearest-channel index per (b, g). Static device global (no allocs).
__device__ int g_idx[NB * NG2];

// ---------------------------------------------------------------------------
// Kernel 1: idx[b,g] = argmin_c ( |loc_c|^2 + |grid_g|^2 - 2 * grid_g . loc_c )
// Emulates XLA-CPU (LLVM, no fp-contract) f32 arithmetic of the reference:
//   a_c  = rn( rn(lx*lx) + rn(ly*ly) )            (mul, mul, add -- no fma)
//   dot  = rn( rn(gx*lx) + rn(gy*ly) )            (V2: mul+add, NO fma)
//   d2   = rn( rn(a_c + b_g) - 2*dot )            (2*dot is exact)
// b_g = gx^2 + gy^2 is integer-exact in f32 (<= 2*99^2 < 2^24).
// Strict '<' keeps the FIRST minimal index, matching jnp.argmin tie-breaking.
// All math through __f*_rn intrinsics so ptxas cannot re-contract to FFMA.
// ---------------------------------------------------------------------------
__global__ void argmin_kernel(const float* __restrict__ locs) {
    __shared__ float s_lx[NC];
    __shared__ float s_ly[NC];
    __shared__ float s_a[NC];

    const int b = blockIdx.y;
    const float* L = locs + (size_t)b * NC * 2;

    for (int c = threadIdx.x; c < NC; c += blockDim.x) {
        float lx = L[2 * c + 0];
        float ly = L[2 * c + 1];
        s_lx[c] = lx;
        s_ly[c] = ly;
        s_a[c]  = __fadd_rn(__fmul_rn(lx, lx), __fmul_rn(ly, ly));
    }
    __syncthreads();

    const int g = blockIdx.x * blockDim.x + threadIdx.x;
    if (g >= NG2) return;

    const int   igx = g / NG;
    const int   igy = g - igx * NG;
    const float gx  = (float)igx;
    const float gy  = (float)igy;
    const float bg  = gx * gx + gy * gy;   // integer-exact regardless of contraction

    float best = 3.0e38f;
    int   bi   = 0;
    for (int c = 0; c < NC; ++c) {
        // V2 dot: separate rounded products, rounded add. NO fma.
        float px  = __fmul_rn(gx, s_lx[c]);
        float py  = __fmul_rn(gy, s_ly[c]);
        float dot = __fadd_rn(px, py);
        float t1  = __fadd_rn(s_a[c], bg);
        float d2  = __fadd_rn(t1, __fmul_rn(-2.0f, dot));  // -2*dot exact
        if (d2 < best) { best = d2; bi = c; }
    }
    g_idx[b * NG2 + g] = bi;
}

// ---------------------------------------------------------------------------
// Kernel 2: out[b,t,g] = data[b,t,idx[b,g]]   -- HBM-write-bound (160 MB out).
// Block handles one (b, t-chunk) x 1024 consecutive g. Per t:
//   - stage the 306-float data row into smem (1.2 KB; avoids L1tex wavefront
//     blowup of random 32-lane LDG gathers),
//   - each thread gathers 4 consecutive g's via LDS (Voronoi runs -> mostly
//     broadcast / low conflict degree) and emits one coalesced STG.128.
// NG2 % 4 == 0 and row starts are multiples of NG2, so float4 stores and the
// int4 index load are aligned.
// ---------------------------------------------------------------------------
__global__ void gather_kernel(const float* __restrict__ data,
                              float* __restrict__ out) {
    __shared__ float s_row[NC];

    const int  b      = blockIdx.z;
    const int  slot   = blockIdx.x * blockDim.x + threadIdx.x;  // group of 4 g
    const bool active = slot < (NG2 / 4);

    int4 idx4 = make_int4(0, 0, 0, 0);
    if (active)
        idx4 = reinterpret_cast<const int4*>(g_idx + b * NG2)[slot];

    const int t0 = blockIdx.y * TCHUNK;
    const float* drow = data + (size_t)(b * NT + t0) * NC;
    float*       orow = out  + (size_t)(b * NT + t0) * NG2 + (size_t)slot * 4;

    #pragma unroll 1
    for (int t = 0; t < TCHUNK; ++t) {
        __syncthreads();   // protect s_row from previous iteration's readers
        for (int c = threadIdx.x; c < NC; c += blockDim.x)
            s_row[c] = drow[c];
        __syncthreads();

        if (active) {
            float4 v;
            v.x = s_row[idx4.x];
            v.y = s_row[idx4.y];
            v.z = s_row[idx4.z];
            v.w = s_row[idx4.w];
            *reinterpret_cast<float4*>(orow) = v;
        }
        drow += NC;
        orow += NG2;
    }
}

// ---------------------------------------------------------------------------
extern "C" void kernel_launch(void* const* d_in, const int* in_sizes, int n_in,
                              void* d_out, int out_size) {
    // metadata order: data (1,224,000 f32), locs (4,896 f32). Select by size
    // to be robust to ordering.
    const float* data = (const float*)d_in[0];
    const float* locs = (const float*)d_in[1];
    if (n_in >= 2 && in_sizes[0] < in_sizes[1]) {
        data = (const float*)d_in[1];
        locs = (const float*)d_in[0];
    }
    float* out = (float*)d_out;

    // Phase 1: nearest-channel index per (b, g).
    {
        dim3 grid((NG2 + 255) / 256, NB, 1);
        argmin_kernel<<<grid, 256>>>(locs);
    }
    // Phase 2: gather (write-bound).
    {
        const int gx = (NG2 / 4 + 255) / 256;   // 10 blocks of 256 slots
        dim3 grid(gx, NT / TCHUNK, NB);          // (10, 25, 8)
        gather_kernel<<<grid, 256>>>(data, out);
    }
    (void)out_size;
}

// round 6
// speedup vs baseline: 1.0146x; 1.0146x over previous
#include <cuda_runtime.h>

// Problem shape (fixed by the reference's setup_inputs):
//   data: (B=8, T=500, C=306) f32      locs: (B=8, C=306, 2) f32
//   out:  (B, T, 100, 100) f32 = gather of nearest channel per grid bin.
#define NB   8
#define NT   500
#define NC   306
#define NG   100
#define NG2  10000       // NG*NG
#define TCHUNK 20        // t rows per gather block (NT / gridDim.y)

// Scratch: nearest-channel index per (b, g). Static device global (no allocs).
__device__ int g_idx[NB * NG2];

// ---------------------------------------------------------------------------
// Kernel 1: idx[b,g] = argmin_c ( |loc_c|^2 + |grid_g|^2 - 2 * grid_g . loc_c )
// Emulates XLA-CPU (LLVM, no fp-contract) f32 arithmetic of the reference:
//   a_c  = rn( rn(lx*lx) + rn(ly*ly) )            (mul, mul, add -- no fma)
//   dot  = rn( rn(gx*lx) + rn(gy*ly) )            (V2: mul+add, NO fma)
//   d2   = rn( rn(a_c + b_g) - 2*dot )            (2*dot is exact)
// b_g = gx^2 + gy^2 is integer-exact in f32 (<= 2*99^2 < 2^24).
// Strict '<' keeps the FIRST minimal index, matching jnp.argmin tie-breaking.
// All math through __f*_rn intrinsics so ptxas cannot re-contract to FFMA.
// ---------------------------------------------------------------------------
__global__ void argmin_kernel(const float* __restrict__ locs) {
    __shared__ float s_lx[NC];
    __shared__ float s_ly[NC];
    __shared__ float s_a[NC];

    const int b = blockIdx.y;
    const float* L = locs + (size_t)b * NC * 2;

    for (int c = threadIdx.x; c < NC; c += blockDim.x) {
        float lx = L[2 * c + 0];
        float ly = L[2 * c + 1];
        s_lx[c] = lx;
        s_ly[c] = ly;
        s_a[c]  = __fadd_rn(__fmul_rn(lx, lx), __fmul_rn(ly, ly));
    }
    __syncthreads();

    const int g = blockIdx.x * blockDim.x + threadIdx.x;
    if (g >= NG2) return;

    const int   igx = g / NG;
    const int   igy = g - igx * NG;
    const float gx  = (float)igx;
    const float gy  = (float)igy;
    const float bg  = gx * gx + gy * gy;   // integer-exact regardless of contraction

    float best = 3.0e38f;
    int   bi   = 0;
    for (int c = 0; c < NC; ++c) {
        // V2 dot: separate rounded products, rounded add. NO fma.
        float px  = __fmul_rn(gx, s_lx[c]);
        float py  = __fmul_rn(gy, s_ly[c]);
        float dot = __fadd_rn(px, py);
        float t1  = __fadd_rn(s_a[c], bg);
        float d2  = __fadd_rn(t1, __fmul_rn(-2.0f, dot));  // -2*dot exact
        if (d2 < best) { best = d2; bi = c; }
    }
    g_idx[b * NG2 + g] = bi;
}

// ---------------------------------------------------------------------------
// Kernel 2: out[b,t,g] = data[b,t,idx[b,g]]   -- HBM-write-bound (160 MB out).
// Block handles one (b, t-chunk) x 1024 consecutive g. Per t:
//   - stage the 306-float data row into smem (1.2 KB; avoids L1tex wavefront
//     blowup of random 32-lane LDG gathers),
//   - each thread gathers 4 consecutive g's via LDS (Voronoi runs -> mostly
//     broadcast / low conflict degree) and emits one coalesced STG.128.
// NG2 % 4 == 0 and row starts are multiples of NG2, so float4 stores and the
// int4 index load are aligned.
// ---------------------------------------------------------------------------
__global__ void gather_kernel(const float* __restrict__ data,
                              float* __restrict__ out) {
    __shared__ float s_row[NC];

    const int  b      = blockIdx.z;
    const int  slot   = blockIdx.x * blockDim.x + threadIdx.x;  // group of 4 g
    const bool active = slot < (NG2 / 4);

    int4 idx4 = make_int4(0, 0, 0, 0);
    if (active)
        idx4 = reinterpret_cast<const int4*>(g_idx + b * NG2)[slot];

    const int t0 = blockIdx.y * TCHUNK;
    const float* drow = data + (size_t)(b * NT + t0) * NC;
    float*       orow = out  + (size_t)(b * NT + t0) * NG2 + (size_t)slot * 4;

    #pragma unroll 1
    for (int t = 0; t < TCHUNK; ++t) {
        __syncthreads();   // protect s_row from previous iteration's readers
        for (int c = threadIdx.x; c < NC; c += blockDim.x)
            s_row[c] = drow[c];
        __syncthreads();

        if (active) {
            float4 v;
            v.x = s_row[idx4.x];
            v.y = s_row[idx4.y];
            v.z = s_row[idx4.z];
            v.w = s_row[idx4.w];
            *reinterpret_cast<float4*>(orow) = v;
        }
        drow += NC;
        orow += NG2;
    }
}

// ---------------------------------------------------------------------------
extern "C" void kernel_launch(void* const* d_in, const int* in_sizes, int n_in,
                              void* d_out, int out_size) {
    // metadata order: data (1,224,000 f32), locs (4,896 f32). Select by size
    // to be robust to ordering.
    const float* data = (const float*)d_in[0];
    const float* locs = (const float*)d_in[1];
    if (n_in >= 2 && in_sizes[0] < in_sizes[1]) {
        data = (const float*)d_in[1];
        locs = (const float*)d_in[0];
    }
    float* out = (float*)d_out;

    // Phase 1: nearest-channel index per (b, g).
    {
        dim3 grid((NG2 + 255) / 256, NB, 1);
        argmin_kernel<<<grid, 256>>>(locs);
    }
    // Phase 2: gather (write-bound).
    {
        const int gx = (NG2 / 4 + 255) / 256;   // 10 blocks of 256 slots
        dim3 grid(gx, NT / TCHUNK, NB);          // (10, 25, 8)
        gather_kernel<<<grid, 256>>>(data, out);
    }
    (void)out_size;
}

// round 7
// speedup vs baseline: 1.6358x; 1.6124x over previous
#include <cuda_runtime.h>

// Problem shape (fixed by the reference's setup_inputs):
//   data: (B=8, T=500, C=306) f32      locs: (B=8, C=306, 2) f32
//   out:  (B, T, 100, 100) f32 = gather of nearest channel per grid bin.
#define NB   8
#define NT   500
#define NC   306
#define NG   100
#define NG2  10000       // NG*NG
#define TCHUNK 20        // t rows per gather block (NT / gridDim.y); keeps
                         // (b*NT+t0)*NC a multiple of 4 -> float4-aligned.

// Scratch: nearest-channel index per (b, g). Static device global (no allocs).
__device__ int g_idx[NB * NG2];

// ---------------------------------------------------------------------------
// Kernel 1: idx[b,g] = argmin_c d2(g,c), bit-exact vs the XLA-CPU reference:
//   a_c  = rn( rn(lx*lx) + rn(ly*ly) )
//   dot  = rn( rn(gx*lx) + rn(gy*ly) )     (no fma)
//   d2   = rn( rn(a_c + bg) - 2*dot )      (2*dot exact)
// Implemented with pre-doubled locs: lx2=2*lx (exact), so
//   dd = rn(gx*lx2 + ... ) -> rn(2px+2py) = 2*rn(px+py)  (pow2 scaling exact)
//   d2 = rn(t1 - dd)  == reference chain bit-for-bit.
// One broadcast LDS.128 per channel instead of three scalar LDS.
// Strict '<' keeps the FIRST minimal index (jnp.argmin tie-break).
// ---------------------------------------------------------------------------
__global__ void argmin_kernel(const float* __restrict__ locs) {
    __shared__ float4 s_lca[NC];   // (2*lx, 2*ly, |l|^2, 0)

    const int b = blockIdx.y;
    const float* L = locs + (size_t)b * NC * 2;

    for (int c = threadIdx.x; c < NC; c += blockDim.x) {
        float lx = L[2 * c + 0];
        float ly = L[2 * c + 1];
        float a  = __fadd_rn(__fmul_rn(lx, lx), __fmul_rn(ly, ly));
        s_lca[c] = make_float4(__fmul_rn(2.0f, lx),   // exact
                               __fmul_rn(2.0f, ly),   // exact
                               a, 0.0f);
    }
    __syncthreads();

    const int g = blockIdx.x * blockDim.x + threadIdx.x;
    if (g >= NG2) return;

    const int   igx = g / NG;
    const int   igy = g - igx * NG;
    const float gx  = (float)igx;
    const float gy  = (float)igy;
    const float bg  = gx * gx + gy * gy;   // integer-exact (< 2^24)

    float best = 3.0e38f;
    int   bi   = 0;
    #pragma unroll 2
    for (int c = 0; c < NC; ++c) {
        float4 v  = s_lca[c];
        float  px = __fmul_rn(gx, v.x);         // 2*rn(gx*lx)
        float  py = __fmul_rn(gy, v.y);         // 2*rn(gy*ly)
        float  dd = __fadd_rn(px, py);          // 2*rn(px'+py')  (exact x2)
        float  t1 = __fadd_rn(v.z, bg);
        float  d2 = __fadd_rn(t1, -dd);         // rn(t1 - 2*dot)
        if (d2 < best) { best = d2; bi = c; }
    }
    g_idx[b * NG2 + g] = bi;
}

// ---------------------------------------------------------------------------
// Kernel 2: out[b,t,g] = data[b,t,idx[b,g]]   -- HBM-write-bound (160 MB out).
// Block = (b, 20-row t-chunk, 1024 consecutive g). The 20 data rows are
// CONTIGUOUS in gmem (24.5 KB): stage them once with coalesced float4 loads,
// one barrier, then 20 independent iterations of 4xLDS + streaming STG.128
// (no barriers -> store pipeline saturates; __stcs avoids L2 write-allocate
// for the 160 MB output that cannot fit in L2 anyway).
// ---------------------------------------------------------------------------
__global__ void gather_kernel(const float* __restrict__ data,
                              float* __restrict__ out) {
    __shared__ float s_data[TCHUNK * NC];      // 24480 B

    const int b    = blockIdx.z;
    const int slot = blockIdx.x * blockDim.x + threadIdx.x;  // group of 4 g
    const int t0   = blockIdx.y * TCHUNK;

    // Stage all 20 rows: contiguous, float4-aligned (see TCHUNK note above).
    const float4* src = reinterpret_cast<const float4*>(
        data + (size_t)(b * NT + t0) * NC);
    #pragma unroll
    for (int i = threadIdx.x; i < (TCHUNK * NC) / 4; i += 256)   // 1530 vec4
        reinterpret_cast<float4*>(s_data)[i] = src[i];
    __syncthreads();

    if (slot < NG2 / 4) {
        const int4 idx4 = reinterpret_cast<const int4*>(g_idx + b * NG2)[slot];
        float*       orow = out + (size_t)(b * NT + t0) * NG2 + (size_t)slot * 4;
        const float* srow = s_data;

        #pragma unroll
        for (int t = 0; t < TCHUNK; ++t) {
            float4 v;
            v.x = srow[idx4.x];
            v.y = srow[idx4.y];
            v.z = srow[idx4.z];
            v.w = srow[idx4.w];
            __stcs(reinterpret_cast<float4*>(orow), v);
            srow += NC;
            orow += NG2;
        }
    }
}

// ---------------------------------------------------------------------------
extern "C" void kernel_launch(void* const* d_in, const int* in_sizes, int n_in,
                              void* d_out, int out_size) {
    // metadata order: data (1,224,000 f32), locs (4,896 f32). Select by size
    // to be robust to ordering.
    const float* data = (const float*)d_in[0];
    const float* locs = (const float*)d_in[1];
    if (n_in >= 2 && in_sizes[0] < in_sizes[1]) {
        data = (const float*)d_in[1];
        locs = (const float*)d_in[0];
    }
    float* out = (float*)d_out;

    // Phase 1: nearest-channel index per (b, g).
    {
        dim3 grid((NG2 + 255) / 256, NB, 1);
        argmin_kernel<<<grid, 256>>>(locs);
    }
    // Phase 2: gather (write-bound).
    {
        const int gx = (NG2 / 4 + 255) / 256;    // 10 blocks of 256 slots
        dim3 grid(gx, NT / TCHUNK, NB);           // (10, 25, 8) = 2000 blocks
        gather_kernel<<<grid, 256>>>(data, out);
    }
    (void)out_size;
}